// round 5
// baseline (speedup 1.0000x reference)
#include <cuda_runtime.h>
#include <cuda_bf16.h>

#define BATCH 2
#define NSEQ 1024
#define DIM 256
#define PDIM 64
#define MAXREL 32
#define NEMBED (2 * MAXREL + 1)

// Scratch: projections (proj_j has bias pre-added)
__device__ float g_proj_i[BATCH * NSEQ * PDIM];
__device__ float g_proj_j[BATCH * NSEQ * PDIM];
// Per-row statistics: {mean, mean-of-squares}
__device__ float2 g_mt_i[BATCH * NSEQ];
__device__ float2 g_mt_j[BATCH * NSEQ];
// Per-pair {mu, rinv} (16 MB, L2-resident)
__device__ __align__(16) float2 g_mr[(size_t)BATCH * NSEQ * NSEQ];

// ---------------------------------------------------------------------------
// Kernel 1: proj_i = single @ W[:256], proj_j = single @ W[256:] + b
// Also emits per-row mean / mean-of-squares for the algebraic LayerNorm.
// ---------------------------------------------------------------------------
__global__ __launch_bounds__(128) void proj_kernel(
    const float* __restrict__ single, const float* __restrict__ W,
    const float* __restrict__ bias)
{
    __shared__ float s[DIM];
    __shared__ float rs[4], rq[4];
    const int r = blockIdx.x;
    const int t = threadIdx.x;
    const float* row = single + (size_t)r * DIM;
    s[t] = row[t];
    s[t + 128] = row[t + 128];
    __syncthreads();

    const int p = t & 63;
    const float* Wp = W + (t >= 64 ? DIM * PDIM : 0) + p;
    float acc = 0.f;
#pragma unroll 8
    for (int d = 0; d < DIM; d++)
        acc = fmaf(s[d], Wp[d * PDIM], acc);

    if (t >= 64) acc += bias[p];   // fold bias into proj_j BEFORE stats

    // reduce sum / sumsq over the 64-thread half (2 warps each)
    float sv = acc, qv = acc * acc;
#pragma unroll
    for (int off = 16; off > 0; off >>= 1) {
        sv += __shfl_xor_sync(0xffffffffu, sv, off);
        qv += __shfl_xor_sync(0xffffffffu, qv, off);
    }
    const int warp = t >> 5;
    if ((t & 31) == 0) { rs[warp] = sv; rq[warp] = qv; }
    __syncthreads();

    if (t < 64)
        g_proj_i[(size_t)r * PDIM + p] = acc;
    else
        g_proj_j[(size_t)r * PDIM + p] = acc;

    const float inv64 = 1.0f / 64.0f;
    if (t == 0)
        g_mt_i[r] = make_float2((rs[0] + rs[1]) * inv64, (rq[0] + rq[1]) * inv64);
    if (t == 64)
        g_mt_j[r] = make_float2((rs[2] + rs[3]) * inv64, (rq[2] + rq[3]) * inv64);
}

// ---------------------------------------------------------------------------
// Kernel 2: 64x64-tile fp32 GEMM: dot(a_i, c_j) -> {mu, rinv} per pair.
//   mu  = m_i + m_j
//   var = (t_i + t_j + dot/32) - mu^2
// ---------------------------------------------------------------------------
__global__ __launch_bounds__(256) void dot_kernel()
{
    __shared__ float sA[64][65];
    __shared__ float sC[64][65];
    __shared__ float2 smtA[64], smtC[64];

    const int b  = blockIdx.z;
    const int bi = blockIdx.x * 64;
    const int bj = blockIdx.y * 64;
    const float* A = g_proj_i + ((size_t)(b * NSEQ) + bi) * PDIM;
    const float* C = g_proj_j + ((size_t)(b * NSEQ) + bj) * PDIM;
    const int t = threadIdx.x;

#pragma unroll
    for (int s2 = 0; s2 < 4; s2++) {
        int idx = t + s2 * 256;          // float4 index 0..1023
        int row = idx >> 4;
        int col = (idx & 15) << 2;
        float4 va = *(const float4*)(A + row * PDIM + col);
        sA[row][col] = va.x; sA[row][col + 1] = va.y;
        sA[row][col + 2] = va.z; sA[row][col + 3] = va.w;
        float4 vc = *(const float4*)(C + row * PDIM + col);
        sC[row][col] = vc.x; sC[row][col + 1] = vc.y;
        sC[row][col + 2] = vc.z; sC[row][col + 3] = vc.w;
    }
    if (t < 64)            smtA[t]      = g_mt_i[b * NSEQ + bi + t];
    else if (t < 128)      smtC[t - 64] = g_mt_j[b * NSEQ + bj + (t - 64)];
    __syncthreads();

    const int tx = t & 15, ty = t >> 4;   // 16x16 threads, 4x4 outputs each
    float acc[4][4] = {};
#pragma unroll 4
    for (int k = 0; k < 64; k++) {
        float ra[4], rc[4];
#pragma unroll
        for (int u = 0; u < 4; u++) ra[u] = sA[ty * 4 + u][k];
#pragma unroll
        for (int v = 0; v < 4; v++) rc[v] = sC[tx * 4 + v][k];
#pragma unroll
        for (int u = 0; u < 4; u++)
#pragma unroll
            for (int v = 0; v < 4; v++)
                acc[u][v] = fmaf(ra[u], rc[v], acc[u][v]);
    }

#pragma unroll
    for (int u = 0; u < 4; u++) {
        const float2 mta = smtA[ty * 4 + u];
        float2 o[4];
#pragma unroll
        for (int v = 0; v < 4; v++) {
            const float2 mtc = smtC[tx * 4 + v];
            float mu  = mta.x + mtc.x;
            float e2  = fmaf(acc[u][v], 1.0f / 32.0f, mta.y + mtc.y);
            float var = fmaf(-mu, mu, e2);
            o[v] = make_float2(mu, rsqrtf(var + 1e-5f));
        }
        float2* dst = g_mr + ((size_t)(b * NSEQ) + bi + ty * 4 + u) * NSEQ + bj + tx * 4;
        *(float4*)(dst)     = make_float4(o[0].x, o[0].y, o[1].x, o[1].y);
        *(float4*)(dst + 2) = make_float4(o[2].x, o[2].y, o[3].x, o[3].y);
    }
}

// ---------------------------------------------------------------------------
// Kernel 3: the big one — NO in-loop reduction.
//   y = relu((a+c)*rg + (beta - mu*rg)) + embed[clip(j-i)]   with rg = rinv*gamma
// Block = (b, i): 8 warps x 2 pairs/warp (16 lanes/pair, float4/lane).
// ---------------------------------------------------------------------------
__global__ __launch_bounds__(256) void pair_kernel(
    const float* __restrict__ gamma, const float* __restrict__ beta,
    const float* __restrict__ embed, float* __restrict__ out)
{
    __shared__ float s_embed[NEMBED * PDIM];              // 16640 B
    __shared__ __align__(16) float2 s_mr[NSEQ];           // 8192 B

    const int i = blockIdx.x;
    const int b = blockIdx.y;

    for (int t4 = threadIdx.x; t4 < (NEMBED * PDIM) / 4; t4 += 256)
        ((float4*)s_embed)[t4] = ((const float4*)embed)[t4];

    const float2* mr = g_mr + ((size_t)(b * NSEQ) + i) * NSEQ;
    for (int t4 = threadIdx.x; t4 < NSEQ / 2; t4 += 256)
        ((float4*)s_mr)[t4] = ((const float4*)mr)[t4];

    const int lane = threadIdx.x & 31;
    const int w = threadIdx.x >> 5;
    const int h = lane >> 4;       // which of the 2 pairs in this warp
    const int li = lane & 15;      // lane within the 16-lane pair group

    const float4 a  = *(const float4*)(g_proj_i + ((size_t)(b * NSEQ + i)) * PDIM + li * 4);
    const float4 gm = *(const float4*)(gamma + li * 4);
    const float4 bt = *(const float4*)(beta + li * 4);

    const float* pj = g_proj_j + (size_t)b * NSEQ * PDIM;
    float* outrow = out + ((size_t)(b * NSEQ + i)) * NSEQ * PDIM + li * 4;

    __syncthreads();

#pragma unroll 4
    for (int jb = 0; jb < NSEQ; jb += 16) {
        const int j = jb + w * 2 + h;
        const float4 c = *(const float4*)(pj + (size_t)j * PDIM + li * 4);
        const float2 mrv = s_mr[j];
        const float mu = mrv.x, rinv = mrv.y;

        float4 x;
        x.x = a.x + c.x; x.y = a.y + c.y; x.z = a.z + c.z; x.w = a.w + c.w;

        const float rgx = rinv * gm.x, rgy = rinv * gm.y;
        const float rgz = rinv * gm.z, rgw = rinv * gm.w;
        const float bx = fmaf(-mu, rgx, bt.x), by = fmaf(-mu, rgy, bt.y);
        const float bz = fmaf(-mu, rgz, bt.z), bw = fmaf(-mu, rgw, bt.w);

        float4 y;
        y.x = fmaxf(fmaf(x.x, rgx, bx), 0.f);
        y.y = fmaxf(fmaf(x.y, rgy, by), 0.f);
        y.z = fmaxf(fmaf(x.z, rgz, bz), 0.f);
        y.w = fmaxf(fmaf(x.w, rgw, bw), 0.f);

        int rel = j - i;
        rel = min(max(rel, -MAXREL), MAXREL) + MAXREL;
        const float4 e = *(const float4*)(s_embed + rel * PDIM + li * 4);
        y.x += e.x; y.y += e.y; y.z += e.z; y.w += e.w;

        *(float4*)(outrow + (size_t)j * PDIM) = y;
    }
}

extern "C" void kernel_launch(void* const* d_in, const int* in_sizes, int n_in,
                              void* d_out, int out_size)
{
    const float* single = (const float*)d_in[0];
    const float* W      = (const float*)d_in[1];
    const float* bias   = (const float*)d_in[2];
    const float* gamma  = (const float*)d_in[3];
    const float* beta   = (const float*)d_in[4];
    const float* embed  = (const float*)d_in[5];
    float* out = (float*)d_out;

    proj_kernel<<<BATCH * NSEQ, 128>>>(single, W, bias);

    dim3 dgrid(NSEQ / 64, NSEQ / 64, BATCH);
    dot_kernel<<<dgrid, 256>>>();

    dim3 grid(NSEQ, BATCH);
    pair_kernel<<<grid, 256>>>(gamma, beta, embed, out);
}

// round 7
// speedup vs baseline: 1.2727x; 1.2727x over previous
#include <cuda_runtime.h>
#include <cuda_bf16.h>

#define BATCH 2
#define NSEQ 1024
#define DIM 256
#define PDIM 64
#define MAXREL 32
#define NEMBED (2 * MAXREL + 1)
#define NROWS (BATCH * NSEQ)

// Scratch: projections (proj_j has bias pre-added)
__device__ float g_proj_i[NROWS * PDIM];
__device__ float g_proj_j[NROWS * PDIM];
// Per-row statistics: {mean, mean-of-squares}
__device__ __align__(16) float2 g_mt_i[NROWS];
__device__ __align__(16) float2 g_mt_j[NROWS];

// ---------------------------------------------------------------------------
// Kernel 1 (same as the fast R4 version): proj_i = single @ W[:256],
// proj_j = single @ W[256:] + b. No stats here — keep it lean.
// ---------------------------------------------------------------------------
__global__ __launch_bounds__(128) void proj_kernel(
    const float* __restrict__ single, const float* __restrict__ W,
    const float* __restrict__ bias)
{
    __shared__ float s[DIM];
    const int r = blockIdx.x;
    const int t = threadIdx.x;
    const float* row = single + (size_t)r * DIM;
    s[t] = row[t];
    s[t + 128] = row[t + 128];
    __syncthreads();

    const int p = t & 63;
    const float* Wp = W + (t >= 64 ? DIM * PDIM : 0) + p;
    float acc = 0.f;
#pragma unroll 8
    for (int d = 0; d < DIM; d++)
        acc = fmaf(s[d], Wp[d * PDIM], acc);

    if (t < 64)
        g_proj_i[(size_t)r * PDIM + p] = acc;
    else
        g_proj_j[(size_t)r * PDIM + p] = acc + bias[p];
}

// ---------------------------------------------------------------------------
// Kernel 2 (tiny): per-row {mean, mean-of-squares} for both projections.
// One warp per row; lane holds float2; 5-round butterfly.
// ---------------------------------------------------------------------------
__global__ __launch_bounds__(256) void stats_kernel()
{
    const int gw = (blockIdx.x * 256 + threadIdx.x) >> 5;   // 0 .. 2*NROWS-1
    const int lane = threadIdx.x & 31;
    const bool is_j = gw >= NROWS;
    const int row = is_j ? gw - NROWS : gw;
    const float* src = is_j ? g_proj_j : g_proj_i;

    const float2 v = *(const float2*)(src + (size_t)row * PDIM + lane * 2);
    float s = v.x + v.y;
    float q = fmaf(v.x, v.x, v.y * v.y);
#pragma unroll
    for (int off = 16; off > 0; off >>= 1) {
        s += __shfl_xor_sync(0xffffffffu, s, off);
        q += __shfl_xor_sync(0xffffffffu, q, off);
    }
    if (lane == 0) {
        const float inv64 = 1.0f / 64.0f;
        float2 o = make_float2(s * inv64, q * inv64);
        if (is_j) g_mt_j[row] = o; else g_mt_i[row] = o;
    }
}

// ---------------------------------------------------------------------------
// Kernel 3: for each (b, i, j):
//   mu  = m_i + m_j                       (no reduction)
//   E2  = t_i + t_j + dot(a_i, c_j)/32    (ONE 4-round shuffle reduction)
//   var = E2 - mu^2
//   y = relu((a+c)*rg + (beta - mu*rg)) + embed[clip(j-i)],  rg = rinv*gamma
// Block = (b, i): 8 warps x 2 pairs/warp (16 lanes/pair, float4/lane).
// ---------------------------------------------------------------------------
__global__ __launch_bounds__(256) void pair_kernel(
    const float* __restrict__ gamma, const float* __restrict__ beta,
    const float* __restrict__ embed, float* __restrict__ out)
{
    __shared__ float s_embed[NEMBED * PDIM];              // 16640 B
    __shared__ __align__(16) float2 s_mt[NSEQ];           // 8192 B

    const int i = blockIdx.x;
    const int b = blockIdx.y;

    for (int t4 = threadIdx.x; t4 < (NEMBED * PDIM) / 4; t4 += 256)
        ((float4*)s_embed)[t4] = ((const float4*)embed)[t4];

    const float2* mtj_src = g_mt_j + b * NSEQ;
    for (int t4 = threadIdx.x; t4 < NSEQ / 2; t4 += 256)
        ((float4*)s_mt)[t4] = ((const float4*)mtj_src)[t4];

    const int lane = threadIdx.x & 31;
    const int w = threadIdx.x >> 5;
    const int h = lane >> 4;       // which of the 2 pairs in this warp
    const int li = lane & 15;      // lane within the 16-lane pair group

    const float4 a  = *(const float4*)(g_proj_i + ((size_t)(b * NSEQ + i)) * PDIM + li * 4);
    const float4 gm = *(const float4*)(gamma + li * 4);
    const float4 bt = *(const float4*)(beta + li * 4);
    const float2 mti = g_mt_i[b * NSEQ + i];

    const float* pj = g_proj_j + (size_t)b * NSEQ * PDIM;
    float* outrow = out + ((size_t)(b * NSEQ + i)) * NSEQ * PDIM + li * 4;

    __syncthreads();

    const float inv32 = 1.0f / 32.0f;

#pragma unroll 4
    for (int jb = 0; jb < NSEQ; jb += 16) {
        const int j = jb + w * 2 + h;
        const float4 c = *(const float4*)(pj + (size_t)j * PDIM + li * 4);

        float4 x;
        x.x = a.x + c.x; x.y = a.y + c.y; x.z = a.z + c.z; x.w = a.w + c.w;

        // partial dot(a, c) for this lane's 4 channels
        float d = fmaf(a.x, c.x, fmaf(a.y, c.y, fmaf(a.z, c.z, a.w * c.w)));
        // reduce over the 16-lane group (xor offsets < 16 stay in-group)
#pragma unroll
        for (int off = 8; off > 0; off >>= 1)
            d += __shfl_xor_sync(0xffffffffu, d, off);

        const float2 mtj = s_mt[j];
        const float mu  = mti.x + mtj.x;
        const float e2  = fmaf(d, inv32, mti.y + mtj.y);
        const float var = fmaf(-mu, mu, e2);
        const float rinv = rsqrtf(var + 1e-5f);

        const float rgx = rinv * gm.x, rgy = rinv * gm.y;
        const float rgz = rinv * gm.z, rgw = rinv * gm.w;
        const float bx = fmaf(-mu, rgx, bt.x), by = fmaf(-mu, rgy, bt.y);
        const float bz = fmaf(-mu, rgz, bt.z), bw = fmaf(-mu, rgw, bt.w);

        float4 y;
        y.x = fmaxf(fmaf(x.x, rgx, bx), 0.f);
        y.y = fmaxf(fmaf(x.y, rgy, by), 0.f);
        y.z = fmaxf(fmaf(x.z, rgz, bz), 0.f);
        y.w = fmaxf(fmaf(x.w, rgw, bw), 0.f);

        int rel = j - i;
        rel = min(max(rel, -MAXREL), MAXREL) + MAXREL;
        const float4 e = *(const float4*)(s_embed + rel * PDIM + li * 4);
        y.x += e.x; y.y += e.y; y.z += e.z; y.w += e.w;

        *(float4*)(outrow + (size_t)j * PDIM) = y;
    }
}

extern "C" void kernel_launch(void* const* d_in, const int* in_sizes, int n_in,
                              void* d_out, int out_size)
{
    const float* single = (const float*)d_in[0];
    const float* W      = (const float*)d_in[1];
    const float* bias   = (const float*)d_in[2];
    const float* gamma  = (const float*)d_in[3];
    const float* beta   = (const float*)d_in[4];
    const float* embed  = (const float*)d_in[5];
    float* out = (float*)d_out;

    proj_kernel<<<NROWS, 128>>>(single, W, bias);

    stats_kernel<<<(2 * NROWS) / 8, 256>>>();

    dim3 grid(NSEQ, BATCH);
    pair_kernel<<<grid, 256>>>(gamma, beta, embed, out);
}

// round 9
// speedup vs baseline: 1.8968x; 1.4904x over previous
#include <cuda_runtime.h>
#include <cuda_bf16.h>

#define BATCH 2
#define NSEQ 1024
#define DIM 256
#define PDIM 64
#define MAXREL 32
#define NEMBED (2 * MAXREL + 1)
#define NROWS (BATCH * NSEQ)
#define IT 4   // i-rows per block in pair_kernel

// Scratch
__device__ float g_proj_i[NROWS * PDIM];
__device__ float g_proj_j[NROWS * PDIM];
__device__ float g_proj_jT[BATCH * PDIM * NSEQ];   // [b][p][j] transposed copy
__device__ __align__(16) float2 g_mt_i[NROWS];     // {mean, mean-of-squares}
__device__ __align__(16) float2 g_mt_j[NROWS];

// ---------------------------------------------------------------------------
// Kernel 1: projections. 4 accumulator chains for ILP; also writes the
// transposed proj_j layout used by pair_kernel's dot prologue.
// ---------------------------------------------------------------------------
__global__ __launch_bounds__(128) void proj_kernel(
    const float* __restrict__ single, const float* __restrict__ W,
    const float* __restrict__ bias)
{
    __shared__ float4 s4[DIM / 4];
    const int r = blockIdx.x;
    const int t = threadIdx.x;
    if (t < DIM / 4)
        s4[t] = ((const float4*)(single + (size_t)r * DIM))[t];
    __syncthreads();

    const int p = t & 63;
    const float* Wp = W + (t >= 64 ? DIM * PDIM : 0) + p;
    float a0 = 0.f, a1 = 0.f, a2 = 0.f, a3 = 0.f;
#pragma unroll 8
    for (int d4 = 0; d4 < DIM / 4; d4++) {
        const float4 sv = s4[d4];
        a0 = fmaf(sv.x, Wp[(d4 * 4 + 0) * PDIM], a0);
        a1 = fmaf(sv.y, Wp[(d4 * 4 + 1) * PDIM], a1);
        a2 = fmaf(sv.z, Wp[(d4 * 4 + 2) * PDIM], a2);
        a3 = fmaf(sv.w, Wp[(d4 * 4 + 3) * PDIM], a3);
    }
    float acc = (a0 + a1) + (a2 + a3);

    if (t < 64) {
        g_proj_i[(size_t)r * PDIM + p] = acc;
    } else {
        acc += bias[p];
        g_proj_j[(size_t)r * PDIM + p] = acc;
        const int b = r >> 10, n = r & (NSEQ - 1);
        g_proj_jT[((size_t)b * PDIM + p) * NSEQ + n] = acc;
    }
}

// ---------------------------------------------------------------------------
// Kernel 2 (tiny): per-row {mean, mean-of-squares} for both projections.
// ---------------------------------------------------------------------------
__global__ __launch_bounds__(256) void stats_kernel()
{
    const int gw = (blockIdx.x * 256 + threadIdx.x) >> 5;
    const int lane = threadIdx.x & 31;
    const bool is_j = gw >= NROWS;
    const int row = is_j ? gw - NROWS : gw;
    const float* src = is_j ? g_proj_j : g_proj_i;

    const float2 v = *(const float2*)(src + (size_t)row * PDIM + lane * 2);
    float s = v.x + v.y;
    float q = fmaf(v.x, v.x, v.y * v.y);
#pragma unroll
    for (int off = 16; off > 0; off >>= 1) {
        s += __shfl_xor_sync(0xffffffffu, s, off);
        q += __shfl_xor_sync(0xffffffffu, q, off);
    }
    if (lane == 0) {
        const float inv64 = 1.0f / 64.0f;
        float2 o = make_float2(s * inv64, q * inv64);
        if (is_j) g_mt_j[row] = o; else g_mt_i[row] = o;
    }
}

// ---------------------------------------------------------------------------
// Kernel 3: block = (b, 4 i-rows).
// Prologue: dot(a_ii, c_j) for all 4x1024 pairs via transposed proj_j
//           (register-tiled, coalesced float4 over j) -> {mu, rinv} in smem.
// Main loop: NO reductions. y = relu((a+c)*rg + (bt - mu*rg)) + e,
//            e from registers for |j-i|>=32 (~94% of pairs), else L1-hot LDG.
// ---------------------------------------------------------------------------
__global__ __launch_bounds__(256) void pair_kernel(
    const float* __restrict__ gamma, const float* __restrict__ beta,
    const float* __restrict__ embed, float* __restrict__ out)
{
    __shared__ __align__(16) float2 s_d[IT][NSEQ];   // {mu, rinv}  32 KB
    __shared__ float s_a[IT][PDIM];                  // 1 KB

    const int i0 = blockIdx.x * IT;
    const int b  = blockIdx.y;
    const int t  = threadIdx.x;

    // stage the 4 a-rows (contiguous)
    s_a[t >> 6][t & 63] = g_proj_i[((size_t)(b * NSEQ + i0)) * PDIM + t];
    __syncthreads();

    // ---- prologue: thread t owns 4 consecutive j, all IT i's ----
    {
        const int j0 = t * 4;
        const float* __restrict__ cT = g_proj_jT + (size_t)b * PDIM * NSEQ + j0;
        float acc[IT][4] = {};
#pragma unroll 4
        for (int p = 0; p < PDIM; p++) {
            const float4 c4 = *(const float4*)(cT + (size_t)p * NSEQ);
#pragma unroll
            for (int ii = 0; ii < IT; ii++) {
                const float av = s_a[ii][p];
                acc[ii][0] = fmaf(av, c4.x, acc[ii][0]);
                acc[ii][1] = fmaf(av, c4.y, acc[ii][1]);
                acc[ii][2] = fmaf(av, c4.z, acc[ii][2]);
                acc[ii][3] = fmaf(av, c4.w, acc[ii][3]);
            }
        }
        float2 mti[IT];
#pragma unroll
        for (int ii = 0; ii < IT; ii++) mti[ii] = g_mt_i[b * NSEQ + i0 + ii];

        const float inv32 = 1.0f / 32.0f;
#pragma unroll
        for (int jj = 0; jj < 4; jj++) {
            const float2 mtj = g_mt_j[b * NSEQ + j0 + jj];
#pragma unroll
            for (int ii = 0; ii < IT; ii++) {
                const float mu  = mti[ii].x + mtj.x;
                const float e2  = fmaf(acc[ii][jj], inv32, mti[ii].y + mtj.y);
                const float var = fmaf(-mu, mu, e2);
                s_d[ii][j0 + jj] = make_float2(mu, rsqrtf(var + 1e-5f));
            }
        }
    }

    const int lane = t & 31;
    const int w = t >> 5;
    const int h = lane >> 4;
    const int li = lane & 15;

    const float4 gm   = *(const float4*)(gamma + li * 4);
    const float4 bt   = *(const float4*)(beta + li * 4);
    const float4 e_lo = *(const float4*)(embed + li * 4);
    const float4 e_hi = *(const float4*)(embed + 2 * MAXREL * PDIM + li * 4);

    __syncthreads();   // s_d ready

    float4 a[IT];
#pragma unroll
    for (int ii = 0; ii < IT; ii++)
        a[ii] = *(const float4*)&s_a[ii][li * 4];

    const float* __restrict__ pj = g_proj_j + (size_t)b * NSEQ * PDIM;
    float* obase = out + ((size_t)(b * NSEQ + i0)) * NSEQ * PDIM + li * 4;

#pragma unroll 2
    for (int jb = 0; jb < NSEQ; jb += 16) {
        const int j = jb + w * 2 + h;
        const float4 c = *(const float4*)(pj + (size_t)j * PDIM + li * 4);

#pragma unroll
        for (int ii = 0; ii < IT; ii++) {
            const float2 mr = s_d[ii][j];
            const float mu = mr.x, rinv = mr.y;

            float4 x;
            x.x = a[ii].x + c.x; x.y = a[ii].y + c.y;
            x.z = a[ii].z + c.z; x.w = a[ii].w + c.w;

            const float rgx = rinv * gm.x, rgy = rinv * gm.y;
            const float rgz = rinv * gm.z, rgw = rinv * gm.w;
            const float bx = fmaf(-mu, rgx, bt.x), by = fmaf(-mu, rgy, bt.y);
            const float bz = fmaf(-mu, rgz, bt.z), bw = fmaf(-mu, rgw, bt.w);

            float4 y;
            y.x = fmaxf(fmaf(x.x, rgx, bx), 0.f);
            y.y = fmaxf(fmaf(x.y, rgy, by), 0.f);
            y.z = fmaxf(fmaf(x.z, rgz, bz), 0.f);
            y.w = fmaxf(fmaf(x.w, rgw, bw), 0.f);

            const int dji = j - (i0 + ii);
            float4 e;
            if (dji <= -MAXREL)      e = e_lo;
            else if (dji >= MAXREL)  e = e_hi;
            else e = *(const float4*)(embed + (dji + MAXREL) * PDIM + li * 4);

            y.x += e.x; y.y += e.y; y.z += e.z; y.w += e.w;

            *(float4*)(obase + (size_t)ii * NSEQ * PDIM + (size_t)j * PDIM) = y;
        }
    }
}

extern "C" void kernel_launch(void* const* d_in, const int* in_sizes, int n_in,
                              void* d_out, int out_size)
{
    const float* single = (const float*)d_in[0];
    const float* W      = (const float*)d_in[1];
    const float* bias   = (const float*)d_in[2];
    const float* gamma  = (const float*)d_in[3];
    const float* beta   = (const float*)d_in[4];
    const float* embed  = (const float*)d_in[5];
    float* out = (float*)d_out;

    proj_kernel<<<NROWS, 128>>>(single, W, bias);

    stats_kernel<<<(2 * NROWS) / 8, 256>>>();

    dim3 grid(NSEQ / IT, BATCH);
    pair_kernel<<<grid, 256>>>(gamma, beta, embed, out);
}